// round 10
// baseline (speedup 1.0000x reference)
#include <cuda_runtime.h>
#include <cuda_bf16.h>
#include <cstdint>

#define NTOT 65536
#define DDIM 512
#define KCL  64

#define BN 128              // d-columns per CTA tile
#define BK 32               // k rows per stage
#define DTILES 4            // DDIM / BN
#define NCHUNKS 74          // grid = 4*74 = 296 CTAs = 2 CTAs/SM, one wave
#define NCTAS (DTILES * NCHUNKS)
#define DEPTH 3             // smem buffers in the producer->consumer ring

#define SF_B 144            // F smem row stride bytes (64 bf16 = 128 + 16 pad)
#define SH_B 272            // H smem row stride bytes (128 bf16 = 256 + 16 pad)

__device__ float        g_partial[KCL * DDIM];  // .bss zero; re-zeroed per call
__device__ float        g_h2sum;
__device__ unsigned int g_count;

__device__ __forceinline__ uint32_t smem_u32(const void* p) {
    return (uint32_t)__cvta_generic_to_shared(p);
}

__device__ __forceinline__ uint32_t pack_bf16(float lo, float hi) {
    uint32_t r;
    asm("cvt.rn.bf16x2.f32 %0, %1, %2;" : "=r"(r) : "f"(hi), "f"(lo));
    return r;
}

__device__ __forceinline__ void ldsm4t(uint32_t* r, uint32_t addr) {
    asm volatile(
        "ldmatrix.sync.aligned.m8n8.x4.trans.shared.b16 {%0,%1,%2,%3}, [%4];"
        : "=r"(r[0]), "=r"(r[1]), "=r"(r[2]), "=r"(r[3]) : "r"(addr));
}

#define BAR_SYNC(id)   asm volatile("bar.sync %0, 256;"   :: "r"(id) : "memory")
#define BAR_ARRIVE(id) asm volatile("bar.arrive %0, 256;" :: "r"(id) : "memory")
// full[buf] = 1+buf (producers arrive, consumers sync)
// empty[buf] = 4+buf (consumers arrive, producers sync)

__global__ __launch_bounds__(256, 2)
void k_fused(const float* __restrict__ H, const float* __restrict__ Fm,
             float* __restrict__ out) {
    __shared__ __align__(16) char Fs[DEPTH][BK * SF_B];   // 3 x 4608 B
    __shared__ __align__(16) char Hs[DEPTH][BK * SH_B];   // 3 x 8704 B
    __shared__ float        redbuf[8];
    __shared__ double       sb[8];
    __shared__ unsigned int s_ticket;

    const int tid  = threadIdx.x;
    const int lane = tid & 31;
    const int wid  = tid >> 5;
    const int d0   = blockIdx.x * BN;
    const int c    = blockIdx.y;

    // 2048 k-blocks over 74 chunks: chunks 0..49 get 28, 50..73 get 27
    const int kb_start = c * 27 + (c < 50 ? c : 50);
    const int ITERS    = 27 + (c < 50 ? 1 : 0);
    const int nb0      = kb_start * BK;

    float h2 = 0.f;

    if (wid >= 4) {
        // ================= PRODUCER: warps 4-7 =================
        const int ptid = tid - 128;
        const int fr = ptid >> 4, fq = ptid & 15;   // F: 4 float4/thread
        const int hr = ptid >> 5, hq = ptid & 31;   // H: 8 float4/thread

        float4 rfv[4], rhv[8];

        auto gload = [&](int it) {
            const int nb = nb0 + it * BK;
#pragma unroll
            for (int j = 0; j < 4; j++)
                rfv[j] = *(const float4*)&Fm[(size_t)(nb + fr + 8 * j) * KCL + fq * 4];
#pragma unroll
            for (int j = 0; j < 8; j++)
                rhv[j] = *(const float4*)&H[(size_t)(nb + hr + 4 * j) * DDIM + d0 + hq * 4];
        };

        auto sstore = [&](int buf) {
            char* fb = Fs[buf];
            char* hb = Hs[buf];
#pragma unroll
            for (int j = 0; j < 4; j++) {
                float4 v = rfv[j];
                *(uint2*)(fb + (fr + 8 * j) * SF_B + fq * 8) =
                    make_uint2(pack_bf16(v.x, v.y), pack_bf16(v.z, v.w));
            }
#pragma unroll
            for (int j = 0; j < 8; j++) {
                float4 v = rhv[j];
                *(uint2*)(hb + (hr + 4 * j) * SH_B + hq * 8) =
                    make_uint2(pack_bf16(v.x, v.y), pack_bf16(v.z, v.w));
                h2 = fmaf(v.x, v.x, h2);
                h2 = fmaf(v.y, v.y, h2);
                h2 = fmaf(v.z, v.z, h2);
                h2 = fmaf(v.w, v.w, h2);
            }
        };

        gload(0);
#pragma unroll 1
        for (int it = 0; it < ITERS; ++it) {
            const int buf = it % DEPTH;
            if (it >= DEPTH) BAR_SYNC(4 + buf);     // wait consumers released buf
            sstore(buf);
            BAR_ARRIVE(1 + buf);                    // publish full
            if (it + 1 < ITERS) gload(it + 1);      // latency covered by ring
        }
    } else {
        // ================= CONSUMER: warps 0-3 =================
        const int wn = wid * 32;
        const int g  = lane >> 2;
        const int t  = lane & 3;

        const uint32_t a_lane = (uint32_t)(((lane >> 4) & 1) * (8 * SF_B)
                                           + (lane & 7) * SF_B
                                           + ((lane >> 3) & 1) * 16);
        const uint32_t b_lane = (uint32_t)(((lane >> 3) & 1) * (8 * SH_B)
                                           + (lane & 7) * SH_B
                                           + ((lane >> 4) & 1) * 16);

        float acc[4][4][4];
#pragma unroll
        for (int a = 0; a < 4; a++)
#pragma unroll
            for (int b = 0; b < 4; b++)
#pragma unroll
                for (int cc = 0; cc < 4; cc++) acc[a][b][cc] = 0.f;

#pragma unroll 1
        for (int it = 0; it < ITERS; ++it) {
            const int buf = it % DEPTH;
            BAR_SYNC(1 + buf);                      // wait buf full
            const uint32_t aBase = smem_u32(Fs[buf]) + a_lane;
            const uint32_t bBase = smem_u32(Hs[buf]) + (uint32_t)(wn * 2) + b_lane;
#pragma unroll
            for (int ks = 0; ks < 2; ks++) {        // two k16 steps per BK=32
                uint32_t a[4][4], b[2][4];
#pragma unroll
                for (int mi = 0; mi < 4; mi++)
                    ldsm4t(a[mi], aBase + ks * (16 * SF_B) + mi * 32);
                ldsm4t(b[0], bBase + ks * (16 * SH_B));
                ldsm4t(b[1], bBase + ks * (16 * SH_B) + 32);
#pragma unroll
                for (int mi = 0; mi < 4; mi++)
#pragma unroll
                    for (int ni = 0; ni < 4; ni++) {
                        const uint32_t b0 = b[ni >> 1][(ni & 1) * 2];
                        const uint32_t b1 = b[ni >> 1][(ni & 1) * 2 + 1];
                        asm volatile(
                            "mma.sync.aligned.m16n8k16.row.col.f32.bf16.bf16.f32 "
                            "{%0,%1,%2,%3}, {%4,%5,%6,%7}, {%8,%9}, {%0,%1,%2,%3};\n"
                            : "+f"(acc[mi][ni][0]), "+f"(acc[mi][ni][1]),
                              "+f"(acc[mi][ni][2]), "+f"(acc[mi][ni][3])
                            : "r"(a[mi][0]), "r"(a[mi][1]),
                              "r"(a[mi][2]), "r"(a[mi][3]),
                              "r"(b0), "r"(b1));
                    }
            }
            BAR_ARRIVE(4 + buf);                    // release buf
        }

        // epilogue: packed float2 L2 atomics into partial G[m][d]
#pragma unroll
        for (int mi = 0; mi < 4; mi++)
#pragma unroll
            for (int ni = 0; ni < 4; ni++) {
                int m = mi * 16 + g;
                int n = d0 + wn + ni * 8 + 2 * t;
                atomicAdd((float2*)&g_partial[m * DDIM + n],
                          make_float2(acc[mi][ni][0], acc[mi][ni][1]));
                atomicAdd((float2*)&g_partial[(m + 8) * DDIM + n],
                          make_float2(acc[mi][ni][2], acc[mi][ni][3]));
            }
    }

    // ---- h2 block reduce (producers carry h2; consumers contribute 0) ----
#pragma unroll
    for (int o = 16; o > 0; o >>= 1) h2 += __shfl_xor_sync(0xffffffffu, h2, o);
    if (lane == 0) redbuf[wid] = h2;
    __syncthreads();
    if (tid == 0) {
        float s = 0.f;
#pragma unroll
        for (int w = 0; w < 8; w++) s += redbuf[w];
        atomicAdd(&g_h2sum, s);
    }

    // ---- last-CTA finalize: square-sum G, write scalar, reset state ----
    __threadfence();
    if (tid == 0) s_ticket = atomicAdd(&g_count, 1u);
    __syncthreads();
    if (s_ticket != NCTAS - 1) return;

    double s = 0.0;
    for (int i = tid; i < KCL * DDIM; i += 256) {
        float v = __ldcg(&g_partial[i]);
        s += (double)v * (double)v;
        g_partial[i] = 0.f;              // re-zero for next graph replay
    }
#pragma unroll
    for (int o = 16; o > 0; o >>= 1) s += __shfl_xor_sync(0xffffffffu, s, o);
    if (lane == 0) sb[wid] = s;
    __syncthreads();
    if (tid == 0) {
        double tot = 0.0;
#pragma unroll
        for (int w = 0; w < 8; w++) tot += sb[w];
        float h2tot = __ldcg(&g_h2sum);
        out[0] = (float)((double)h2tot - tot);
        g_h2sum = 0.f;
        g_count = 0u;
    }
}

extern "C" void kernel_launch(void* const* d_in, const int* in_sizes, int n_in,
                              void* d_out, int out_size) {
    const float* Hp;
    const float* Fp;
    if (in_sizes[0] == NTOT * DDIM) {
        Hp = (const float*)d_in[0];
        Fp = (const float*)d_in[1];
    } else {
        Hp = (const float*)d_in[1];
        Fp = (const float*)d_in[0];
    }

    dim3 grid(DTILES, NCHUNKS);
    k_fused<<<grid, 256>>>(Hp, Fp, (float*)d_out);
}